// round 1
// baseline (speedup 1.0000x reference)
#include <cuda_runtime.h>
#include <stdint.h>
#include <math.h>

#define BATCH 16384
#define MDIM  256
#define NDIM  1024
#define DEPTH 16

// ---------------- device scratch (no allocations allowed) ----------------
__device__ float g_r [BATCH * MDIM];          // residual  [B, M]   16 MB
__device__ float g_u [BATCH * NDIM];          // u ping buffer      64 MB
__device__ float g_At[NDIM * MDIM];           // A^T  [N, M]         1 MB
__device__ float g_Wt[DEPTH * MDIM * NDIM];   // W^T  [depth, M, N] 16 MB

// ---------------- transposes (once per launch, tiny) ----------------
__global__ void k_transA(const float* __restrict__ A) {
    int idx = blockIdx.x * 256 + threadIdx.x;          // idx = n*M + m (write-coalesced)
    if (idx < NDIM * MDIM) {
        int n = idx / MDIM, m = idx % MDIM;
        g_At[idx] = A[m * NDIM + n];
    }
}
__global__ void k_transW(const float* __restrict__ W) {
    int idx = blockIdx.x * 256 + threadIdx.x;          // idx = i*M*N + m*N + n
    int n    = idx & (NDIM - 1);
    int rest = idx >> 10;                               // i*M + m
    int m    = rest & (MDIM - 1);
    int i    = rest >> 8;
    g_Wt[idx] = W[i * (NDIM * MDIM) + n * MDIM + m];
}

// ---------------- K1: r = x - u @ A^T   (tile 128 rows x 256 cols, K=1024) --------
__global__ void __launch_bounds__(256, 1) k_resid(
    const float* __restrict__ x, const float* __restrict__ dout, int sel_in)
{
    __shared__ float u_s[8][128];
    __shared__ float a_s[8][256];
    const int tid   = threadIdx.x;
    const int b0    = blockIdx.x * 128;
    const int rbase = (tid >> 4) * 8;       // 8 rows / thread
    const int cbase = (tid & 15) * 4;       // cols cbase + j*64, j<4 (16 cols/thread)

    float acc[8][16];
    #pragma unroll
    for (int i = 0; i < 8; i++)
        #pragma unroll
        for (int c = 0; c < 16; c++) acc[i][c] = 0.f;

    if (sel_in != 0) {
        const float* u_in = (sel_in == 1) ? g_u : dout;
        const int lrow = tid >> 1;
        const int lc4  = (tid & 1) * 4;
        const int ann  = tid >> 5;          // 0..7
        const int amm  = (tid & 31) * 8;    // 0..248
        for (int kc = 0; kc < NDIM; kc += 8) {
            float4 uv = *(const float4*)(u_in + (size_t)(b0 + lrow) * NDIM + kc + lc4);
            float4 a0 = *(const float4*)(g_At + (size_t)(kc + ann) * MDIM + amm);
            float4 a1 = *(const float4*)(g_At + (size_t)(kc + ann) * MDIM + amm + 4);
            __syncthreads();
            u_s[lc4+0][lrow] = uv.x; u_s[lc4+1][lrow] = uv.y;
            u_s[lc4+2][lrow] = uv.z; u_s[lc4+3][lrow] = uv.w;
            *(float4*)&a_s[ann][amm]     = a0;
            *(float4*)&a_s[ann][amm + 4] = a1;
            __syncthreads();
            #pragma unroll
            for (int k = 0; k < 8; k++) {
                float a[8];
                #pragma unroll
                for (int i = 0; i < 8; i++) a[i] = u_s[k][rbase + i];
                #pragma unroll
                for (int j = 0; j < 4; j++) {
                    float4 w = *(float4*)&a_s[k][cbase + j * 64];
                    #pragma unroll
                    for (int i = 0; i < 8; i++) {
                        acc[i][j*4+0] += a[i] * w.x;
                        acc[i][j*4+1] += a[i] * w.y;
                        acc[i][j*4+2] += a[i] * w.z;
                        acc[i][j*4+3] += a[i] * w.w;
                    }
                }
            }
        }
    }
    #pragma unroll
    for (int i = 0; i < 8; i++) {
        size_t rowoff = (size_t)(b0 + rbase + i) * MDIM;
        #pragma unroll
        for (int j = 0; j < 4; j++) {
            size_t off = rowoff + cbase + j * 64;
            float4 xv = *(const float4*)(x + off);
            float4 o  = make_float4(xv.x - acc[i][j*4+0], xv.y - acc[i][j*4+1],
                                    xv.z - acc[i][j*4+2], xv.w - acc[i][j*4+3]);
            *(float4*)(g_r + off) = o;
        }
    }
}

// ---------------- helper: masked shrink ----------------
__device__ __forceinline__ float sel_shrink(float v, float t, float tv) {
    float av = fabsf(v);
    if (av >= t && av >= tv) return v;          // support-selected: pass through
    return copysignf(fmaxf(av - t, 0.f), v);    // soft threshold
}

// ---- K2: v = u + r @ W_i^T, exact per-row k-th-largest select, shrink, write u ----
// CTA: 32 rows x 1024 cols, 256 threads (8 rows x 16 cols each), K=256 chunks of 8.
__global__ void __launch_bounds__(256, 1) k_step(
    float* __restrict__ dout, const float* __restrict__ thr,
    int layer, int kth, int sel_in, int sel_out)
{
    __shared__ float r_s[8][32];
    __shared__ __align__(16) unsigned char sm_raw[32 * 257 * 4];  // union: w_s / hist
    float        (*w_s)[1024] = (float        (*)[1024])sm_raw;   // 32 KB
    unsigned int (*hist)[257] = (unsigned int (*)[257])sm_raw;    // 32.9 KB (padded)
    __shared__ unsigned int s_prefix[32];
    __shared__ int          s_krem[32];

    const int  tid  = threadIdx.x;
    const int  lane = tid & 31;
    const long b0   = (long)blockIdx.x * 32;
    const int  rgrp = tid >> 6;       // rows rgrp*8 + rr
    const int  cgrp = tid & 63;       // cols cgrp*4 + j*256

    float acc[8][16];
    #pragma unroll
    for (int rr = 0; rr < 8; rr++)
        #pragma unroll
        for (int c = 0; c < 16; c++) acc[rr][c] = 0.f;

    const float* Wt = g_Wt + (size_t)layer * MDIM * NDIM;
    for (int kc = 0; kc < MDIM; kc += 8) {
        float4 wreg[8];
        const float4* src = (const float4*)(Wt + (size_t)kc * NDIM);
        #pragma unroll
        for (int q = 0; q < 8; q++) wreg[q] = src[tid + 256 * q];
        float rreg = g_r[(size_t)(b0 + (tid >> 3)) * MDIM + kc + (tid & 7)];
        __syncthreads();
        #pragma unroll
        for (int q = 0; q < 8; q++) ((float4*)w_s)[tid + 256 * q] = wreg[q];
        r_s[tid & 7][tid >> 3] = rreg;
        __syncthreads();
        #pragma unroll
        for (int k = 0; k < 8; k++) {
            float a[8];
            #pragma unroll
            for (int rr = 0; rr < 8; rr++) a[rr] = r_s[k][rgrp * 8 + rr];
            #pragma unroll
            for (int j = 0; j < 4; j++) {
                float4 w = *(float4*)&w_s[k][cgrp * 4 + j * 256];
                #pragma unroll
                for (int rr = 0; rr < 8; rr++) {
                    acc[rr][j*4+0] += a[rr] * w.x;
                    acc[rr][j*4+1] += a[rr] * w.y;
                    acc[rr][j*4+2] += a[rr] * w.z;
                    acc[rr][j*4+3] += a[rr] * w.w;
                }
            }
        }
    }

    // v = u + acc
    const float t = thr[layer];
    if (sel_in != 0) {
        const float* u_in = (sel_in == 1) ? g_u : dout;
        #pragma unroll
        for (int rr = 0; rr < 8; rr++) {
            size_t ro = (size_t)(b0 + rgrp * 8 + rr) * NDIM;
            #pragma unroll
            for (int j = 0; j < 4; j++) {
                float4 uv = *(const float4*)(u_in + ro + cgrp * 4 + j * 256);
                acc[rr][j*4+0] += uv.x; acc[rr][j*4+1] += uv.y;
                acc[rr][j*4+2] += uv.z; acc[rr][j*4+3] += uv.w;
            }
        }
    }

    // ---- exact k-th largest of |v| per row: 4-pass byte radix on fp32 bits ----
    __syncthreads();                                    // done reading w_s
    for (int q = tid; q < 32 * 257; q += 256) ((unsigned int*)hist)[q] = 0u;
    if (tid < 32) { s_prefix[tid] = 0u; s_krem[tid] = kth; }
    __syncthreads();

    #pragma unroll
    for (int p = 0; p < 4; p++) {
        const int shift = 24 - 8 * p;
        const unsigned int himask = (p == 0) ? 0u : (0xFFFFFFFFu << (shift + 8));
        unsigned int pfx[8];
        #pragma unroll
        for (int rr = 0; rr < 8; rr++) pfx[rr] = s_prefix[rgrp * 8 + rr];
        #pragma unroll
        for (int rr = 0; rr < 8; rr++) {
            const int row = rgrp * 8 + rr;
            #pragma unroll
            for (int idx = 0; idx < 16; idx++) {
                unsigned int key = __float_as_uint(acc[rr][idx]) & 0x7FFFFFFFu;
                bool active = ((key & himask) == pfx[rr]);
                unsigned int bal = __ballot_sync(0xFFFFFFFFu, active);
                if (active) {
                    unsigned int bin  = (key >> shift) & 0xFFu;
                    unsigned int same = __match_any_sync(bal, bin);
                    if ((int)(__ffs(same) - 1) == lane)
                        atomicAdd(&hist[row][bin], (unsigned int)__popc(same));
                }
            }
        }
        __syncthreads();
        if (tid < 32) {                                  // one thread per row: scan bins
            int krem = s_krem[tid];
            unsigned int cum = 0; int sel = 0;
            for (int b = 255; b >= 0; b--) {
                unsigned int c = hist[tid][b];
                if (cum + c >= (unsigned int)krem) { sel = b; break; }
                cum += c;
            }
            s_krem[tid]    = krem - (int)cum;
            s_prefix[tid] |= ((unsigned int)sel) << shift;
        }
        __syncthreads();
        if (p < 3) {
            for (int q = tid; q < 32 * 257; q += 256) ((unsigned int*)hist)[q] = 0u;
            __syncthreads();
        }
    }

    // ---- mask + shrink + store u_next ----
    float* u_out = (sel_out == 1) ? g_u : dout;
    #pragma unroll
    for (int rr = 0; rr < 8; rr++) {
        const int row = rgrp * 8 + rr;
        const float tv = __uint_as_float(s_prefix[row]);
        size_t ro = (size_t)(b0 + row) * NDIM;
        #pragma unroll
        for (int j = 0; j < 4; j++) {
            float4 o;
            o.x = sel_shrink(acc[rr][j*4+0], t, tv);
            o.y = sel_shrink(acc[rr][j*4+1], t, tv);
            o.z = sel_shrink(acc[rr][j*4+2], t, tv);
            o.w = sel_shrink(acc[rr][j*4+3], t, tv);
            *(float4*)(u_out + ro + cgrp * 4 + j * 256) = o;
        }
    }
}

// ---------------- launch ----------------
extern "C" void kernel_launch(void* const* d_in, const int* in_sizes, int n_in,
                              void* d_out, int out_size) {
    const float* x   = (const float*)d_in[0];
    const float* A   = (const float*)d_in[1];
    const float* W   = (const float*)d_in[2];
    const float* thr = (const float*)d_in[3];
    float* out = (float*)d_out;

    k_transA<<<(NDIM * MDIM + 255) / 256, 256>>>(A);
    k_transW<<<(DEPTH * MDIM * NDIM) / 256, 256>>>(W);

    for (int i = 0; i < DEPTH; i++) {
        double p = (i + 1) * 1.2; if (p > 5.0) p = 5.0;
        int idx = (int)ceil((100.0 - p) / 100.0 * (double)NDIM) - 1;
        int kth = NDIM - idx;                       // k-th largest (13,25,37,50,52,...)
        int sel_in  = (i == 0) ? 0 : ((i & 1) ? 1 : 2);
        int sel_out = (i & 1) ? 2 : 1;              // iter 15 (odd) -> d_out
        k_resid<<<BATCH / 128, 256>>>(x, out, sel_in);
        k_step <<<BATCH / 32,  256>>>(out, thr, i, kth, sel_in, sel_out);
    }
}

// round 14
// speedup vs baseline: 1.1010x; 1.1010x over previous
#include <cuda_runtime.h>
#include <stdint.h>
#include <math.h>

#define BATCH 16384
#define MDIM  256
#define NDIM  1024
#define DEPTH 16

// ---------------- device scratch ----------------
__device__ float          g_u   [BATCH * NDIM];       // dense u (fp32)
__device__ float          g_r   [BATCH * MDIM];       // residual
__device__ float          g_At  [NDIM * MDIM];        // A^T: [k][m]
__device__ float          g_Wt  [DEPTH * MDIM * NDIM];// W^T per layer: [k][n]
__device__ unsigned short g_sk  [BATCH * NDIM];       // support k-indices (ascending)
__device__ float          g_sv  [BATCH * NDIM];       // support u values
__device__ int            g_scnt[BATCH];

// ---------------- prep transposes ----------------
__global__ void k_transA(const float* __restrict__ A) {
    int idx = blockIdx.x * 256 + threadIdx.x;          // idx = k*256 + m
    if (idx >= NDIM * MDIM) return;
    int k = idx >> 8, m = idx & 255;
    g_At[idx] = A[m * NDIM + k];
}
__global__ void k_transW(const float* __restrict__ W) {
    int idx = blockIdx.x * 256 + threadIdx.x;          // idx = i*(M*N) + k*N + n
    if (idx >= DEPTH * MDIM * NDIM) return;
    int n = idx & (NDIM - 1);
    int rest = idx >> 10;
    int m = rest & (MDIM - 1);
    int i = rest >> 8;
    g_Wt[idx] = W[i * (NDIM * MDIM) + n * MDIM + m];
}

// ------- sparse residual: r = x - u@A^T, skipping u_k == 0 (bit-exact) -------
// warp per row; lane owns 8 m-columns (lane*8 .. +7); k ascending
__global__ void __launch_bounds__(256, 1) k_rsparse(const float* __restrict__ x) {
    const int tid = threadIdx.x, lane = tid & 31;
    const long row = (long)blockIdx.x * 8 + (tid >> 5);
    const int cnt = g_scnt[row];
    const unsigned short* __restrict__ ks = g_sk + (size_t)row * NDIM;
    const float*          __restrict__ vs = g_sv + (size_t)row * NDIM;
    const int m0 = lane * 8;

    float acc[8];
    #pragma unroll
    for (int j = 0; j < 8; j++) acc[j] = 0.f;

    for (int s = 0; s < cnt; s++) {
        int k = ks[s]; float v = vs[s];
        float4 al = *(const float4*)&g_At[k * MDIM + m0];
        float4 ah = *(const float4*)&g_At[k * MDIM + m0 + 4];
        acc[0] = fmaf(v, al.x, acc[0]); acc[1] = fmaf(v, al.y, acc[1]);
        acc[2] = fmaf(v, al.z, acc[2]); acc[3] = fmaf(v, al.w, acc[3]);
        acc[4] = fmaf(v, ah.x, acc[4]); acc[5] = fmaf(v, ah.y, acc[5]);
        acc[6] = fmaf(v, ah.z, acc[6]); acc[7] = fmaf(v, ah.w, acc[7]);
    }

    size_t go = (size_t)row * MDIM + m0;
    float4 x0 = *(const float4*)&x[go];
    float4 x1 = *(const float4*)&x[go + 4];
    *(float4*)&g_r[go]     = make_float4(x0.x - acc[0], x0.y - acc[1],
                                         x0.z - acc[2], x0.w - acc[3]);
    *(float4*)&g_r[go + 4] = make_float4(x1.x - acc[4], x1.y - acc[5],
                                         x1.z - acc[6], x1.w - acc[7]);
}

// ---------------- helper: masked shrink ----------------
__device__ __forceinline__ float sel_shrink(float v, float t, float tv) {
    float av = fabsf(v);
    if (av >= t && av >= tv) return v;          // support-selected: pass through
    return copysignf(fmaxf(av - t, 0.f), v);    // soft threshold
}

// ---- k_step: v = u + r @ W_i^T, exact per-row k-th-largest select, shrink, write u ----
// (R1-proven kernel: CTA 32 rows x 1024 cols, 256 threads, K chunks of 8)
// r source / u destination selected by flags INSIDE device code (never pass
// __device__ symbols from host — host shadow address + ATS = 128MiB violation).
__global__ void __launch_bounds__(256, 1) k_step(
    const float* __restrict__ x, float* out,
    const float* __restrict__ thr, int layer, int kth,
    int add_u, int r_from_x, int write_out)
{
    __shared__ float r_s[8][32];
    __shared__ __align__(16) unsigned char sm_raw[32 * 257 * 4];  // union: w_s / hist
    float        (*w_s)[1024] = (float        (*)[1024])sm_raw;   // 32 KB
    unsigned int (*hist)[257] = (unsigned int (*)[257])sm_raw;    // 32.9 KB (padded)
    __shared__ unsigned int s_prefix[32];
    __shared__ int          s_krem[32];

    const float* r_in = r_from_x ? x : g_r;
    float*       uout = write_out ? out : g_u;

    const int  tid  = threadIdx.x;
    const int  lane = tid & 31;
    const long b0   = (long)blockIdx.x * 32;
    const int  rgrp = tid >> 6;       // rows rgrp*8 + rr
    const int  cgrp = tid & 63;       // cols cgrp*4 + j*256

    float acc[8][16];
    #pragma unroll
    for (int rr = 0; rr < 8; rr++)
        #pragma unroll
        for (int c = 0; c < 16; c++) acc[rr][c] = 0.f;

    const float* Wt = g_Wt + (size_t)layer * MDIM * NDIM;
    for (int kc = 0; kc < MDIM; kc += 8) {
        float4 wreg[8];
        const float4* src = (const float4*)(Wt + (size_t)kc * NDIM);
        #pragma unroll
        for (int q = 0; q < 8; q++) wreg[q] = src[tid + 256 * q];
        float rreg = r_in[(size_t)(b0 + (tid >> 3)) * MDIM + kc + (tid & 7)];
        __syncthreads();
        #pragma unroll
        for (int q = 0; q < 8; q++) ((float4*)w_s)[tid + 256 * q] = wreg[q];
        r_s[tid & 7][tid >> 3] = rreg;
        __syncthreads();
        #pragma unroll
        for (int k = 0; k < 8; k++) {
            float a[8];
            #pragma unroll
            for (int rr = 0; rr < 8; rr++) a[rr] = r_s[k][rgrp * 8 + rr];
            #pragma unroll
            for (int j = 0; j < 4; j++) {
                float4 w = *(float4*)&w_s[k][cgrp * 4 + j * 256];
                #pragma unroll
                for (int rr = 0; rr < 8; rr++) {
                    acc[rr][j*4+0] += a[rr] * w.x;
                    acc[rr][j*4+1] += a[rr] * w.y;
                    acc[rr][j*4+2] += a[rr] * w.z;
                    acc[rr][j*4+3] += a[rr] * w.w;
                }
            }
        }
    }

    // v = u + acc
    const float t = thr[layer];
    if (add_u) {
        #pragma unroll
        for (int rr = 0; rr < 8; rr++) {
            size_t ro = (size_t)(b0 + rgrp * 8 + rr) * NDIM;
            #pragma unroll
            for (int j = 0; j < 4; j++) {
                float4 uv = *(const float4*)(g_u + ro + cgrp * 4 + j * 256);
                acc[rr][j*4+0] += uv.x; acc[rr][j*4+1] += uv.y;
                acc[rr][j*4+2] += uv.z; acc[rr][j*4+3] += uv.w;
            }
        }
    }

    // ---- exact k-th largest of |v| per row: 4-pass byte radix on fp32 bits ----
    __syncthreads();                                    // done reading w_s
    for (int q = tid; q < 32 * 257; q += 256) ((unsigned int*)hist)[q] = 0u;
    if (tid < 32) { s_prefix[tid] = 0u; s_krem[tid] = kth; }
    __syncthreads();

    #pragma unroll
    for (int p = 0; p < 4; p++) {
        const int shift = 24 - 8 * p;
        const unsigned int himask = (p == 0) ? 0u : (0xFFFFFFFFu << (shift + 8));
        unsigned int pfx[8];
        #pragma unroll
        for (int rr = 0; rr < 8; rr++) pfx[rr] = s_prefix[rgrp * 8 + rr];
        #pragma unroll
        for (int rr = 0; rr < 8; rr++) {
            const int row = rgrp * 8 + rr;
            #pragma unroll
            for (int idx = 0; idx < 16; idx++) {
                unsigned int key = __float_as_uint(acc[rr][idx]) & 0x7FFFFFFFu;
                bool active = ((key & himask) == pfx[rr]);
                unsigned int bal = __ballot_sync(0xFFFFFFFFu, active);
                if (active) {
                    unsigned int bin  = (key >> shift) & 0xFFu;
                    unsigned int same = __match_any_sync(bal, bin);
                    if ((int)(__ffs(same) - 1) == lane)
                        atomicAdd(&hist[row][bin], (unsigned int)__popc(same));
                }
            }
        }
        __syncthreads();
        if (tid < 32) {                                  // one thread per row: scan bins
            int krem = s_krem[tid];
            unsigned int cum = 0; int sel = 0;
            for (int b = 255; b >= 0; b--) {
                unsigned int c = hist[tid][b];
                if (cum + c >= (unsigned int)krem) { sel = b; break; }
                cum += c;
            }
            s_krem[tid]    = krem - (int)cum;
            s_prefix[tid] |= ((unsigned int)sel) << shift;
        }
        __syncthreads();
        if (p < 3) {
            for (int q = tid; q < 32 * 257; q += 256) ((unsigned int*)hist)[q] = 0u;
            __syncthreads();
        }
    }

    // ---- mask + shrink + store u_next ----
    #pragma unroll
    for (int rr = 0; rr < 8; rr++) {
        const int row = rgrp * 8 + rr;
        const float tv = __uint_as_float(s_prefix[row]);
        size_t ro = (size_t)(b0 + row) * NDIM;
        #pragma unroll
        for (int j = 0; j < 4; j++) {
            float4 o;
            o.x = sel_shrink(acc[rr][j*4+0], t, tv);
            o.y = sel_shrink(acc[rr][j*4+1], t, tv);
            o.z = sel_shrink(acc[rr][j*4+2], t, tv);
            o.w = sel_shrink(acc[rr][j*4+3], t, tv);
            *(float4*)(uout + ro + cgrp * 4 + j * 256) = o;
        }
    }
}

// ------- compaction: dense u -> ascending (k, value) support lists -------
// warp per row; ballot-based
__global__ void __launch_bounds__(256, 1) k_compact() {
    const int tid = threadIdx.x, lane = tid & 31;
    const long row = (long)blockIdx.x * 8 + (tid >> 5);
    const float* ur = g_u + (size_t)row * NDIM;
    unsigned short* sk = g_sk + (size_t)row * NDIM;
    float*          sv = g_sv + (size_t)row * NDIM;

    int base = 0;
    #pragma unroll
    for (int j = 0; j < 8; j++) {
        int kbase = (lane + j * 32) * 4;
        float4 u4 = *(const float4*)(ur + kbase);
        float o[4] = {u4.x, u4.y, u4.z, u4.w};
        unsigned m = (o[0] != 0.f ? 1u : 0u) | (o[1] != 0.f ? 2u : 0u)
                   | (o[2] != 0.f ? 4u : 0u) | (o[3] != 0.f ? 8u : 0u);
        int pc = __popc(m);
        int pre = pc;
        #pragma unroll
        for (int off = 1; off < 32; off <<= 1) {
            int t2 = __shfl_up_sync(0xFFFFFFFFu, pre, off);
            if (lane >= off) pre += t2;
        }
        int excl = pre - pc;
        int tot  = __shfl_sync(0xFFFFFFFFu, pre, 31);
        int slot0 = base + excl;
        #pragma unroll
        for (int cc = 0; cc < 4; cc++) {
            if (m & (1u << cc)) {
                int slot = slot0 + __popc(m & ((1u << cc) - 1));
                sk[slot] = (unsigned short)(kbase + cc);
                sv[slot] = o[cc];
            }
        }
        base += tot;
    }
    if (lane == 0) g_scnt[row] = base;
}

// ---------------- launch (NO __device__ symbols in any host expression) ----------------
extern "C" void kernel_launch(void* const* d_in, const int* in_sizes, int n_in,
                              void* d_out, int out_size) {
    const float* x   = (const float*)d_in[0];
    const float* A   = (const float*)d_in[1];
    const float* W   = (const float*)d_in[2];
    const float* thr = (const float*)d_in[3];
    float* out = (float*)d_out;

    k_transA<<<(NDIM * MDIM + 255) / 256, 256>>>(A);
    k_transW<<<(DEPTH * MDIM * NDIM + 255) / 256, 256>>>(W);

    for (int i = 0; i < DEPTH; i++) {
        double p = (i + 1) * 1.2; if (p > 5.0) p = 5.0;
        int idx = (int)ceil((100.0 - p) / 100.0 * (double)NDIM) - 1;
        int kth = NDIM - idx;                       // k-th largest
        if (i > 0)
            k_rsparse<<<BATCH / 8, 256>>>(x);
        k_step<<<BATCH / 32, 256>>>(x, out, thr, i, kth,
                                    (i > 0) ? 1 : 0,            // add_u
                                    (i == 0) ? 1 : 0,           // r_from_x
                                    (i == DEPTH - 1) ? 1 : 0);  // write_out
        if (i < DEPTH - 1)
            k_compact<<<BATCH / 8, 256>>>();
    }
}

// round 17
// speedup vs baseline: 1.1503x; 1.0448x over previous
#include <cuda_runtime.h>
#include <stdint.h>
#include <math.h>

#define BATCH 16384
#define MDIM  256
#define NDIM  1024
#define DEPTH 16

// k_step pipeline: chunk = 8 k-slices; stage = W(8x1024 f32) + r(8x32 f32)
#define W_FLOATS   (8 * 1024)                 // 8192
#define R_FLOATS   (8 * 32)                   // 256
#define STG_FLOATS (W_FLOATS + R_FLOATS)      // 8448
#define N_STAGES   3
#define DYN_STEP   (N_STAGES * STG_FLOATS * 4)   // 101376 B

// ---------------- device scratch ----------------
__device__ float          g_u   [BATCH * NDIM];       // dense u (fp32)
__device__ float          g_r   [BATCH * MDIM];       // residual
__device__ float          g_At  [NDIM * MDIM];        // A^T: [k][m]
__device__ float          g_Wt  [DEPTH * MDIM * NDIM];// W^T per layer: [k][n]
__device__ unsigned short g_sk  [BATCH * NDIM];       // support k-indices (ascending)
__device__ float          g_sv  [BATCH * NDIM];       // support u values
__device__ int            g_scnt[BATCH];

// ---------------- helpers ----------------
__device__ __forceinline__ uint32_t smem_u32(const void* p) {
    uint32_t a;
    asm("{ .reg .u64 t; cvta.to.shared.u64 t, %1; cvt.u32.u64 %0, t; }" : "=r"(a) : "l"(p));
    return a;
}
__device__ __forceinline__ void cp16(uint32_t saddr, const void* g) {
    asm volatile("cp.async.cg.shared.global [%0], [%1], 16;" :: "r"(saddr), "l"(g));
}
__device__ __forceinline__ void cp4(uint32_t saddr, const void* g) {
    asm volatile("cp.async.ca.shared.global [%0], [%1], 4;" :: "r"(saddr), "l"(g));
}
#define CP_COMMIT() asm volatile("cp.async.commit_group;" ::: "memory")
#define CP_WAIT1()  asm volatile("cp.async.wait_group 1;" ::: "memory")
#define CP_WAIT0()  asm volatile("cp.async.wait_group 0;" ::: "memory")

// ---------------- prep transposes ----------------
__global__ void k_transA(const float* __restrict__ A) {
    int idx = blockIdx.x * 256 + threadIdx.x;          // idx = k*256 + m
    if (idx >= NDIM * MDIM) return;
    int k = idx >> 8, m = idx & 255;
    g_At[idx] = A[m * NDIM + k];
}
__global__ void k_transW(const float* __restrict__ W) {
    int idx = blockIdx.x * 256 + threadIdx.x;          // idx = i*(M*N) + k*N + n
    if (idx >= DEPTH * MDIM * NDIM) return;
    int n = idx & (NDIM - 1);
    int rest = idx >> 10;
    int m = rest & (MDIM - 1);
    int i = rest >> 8;
    g_Wt[idx] = W[i * (NDIM * MDIM) + n * MDIM + m];
}

// ------- sparse residual: r = x - u@A^T, skipping u_k == 0 (bit-exact) -------
// warp per row; lane owns 8 m-columns; 4-wide unroll for load MLP (chain order
// per accumulator is still strictly ascending s — bit-exact).
__global__ void __launch_bounds__(256, 1) k_rsparse(const float* __restrict__ x) {
    const int tid = threadIdx.x, lane = tid & 31;
    const long row = (long)blockIdx.x * 8 + (tid >> 5);
    const int cnt = g_scnt[row];
    const unsigned short* __restrict__ ks = g_sk + (size_t)row * NDIM;
    const float*          __restrict__ vs = g_sv + (size_t)row * NDIM;
    const int m0 = lane * 8;

    float acc[8];
    #pragma unroll
    for (int j = 0; j < 8; j++) acc[j] = 0.f;

    int s = 0;
    for (; s + 4 <= cnt; s += 4) {
        int   k0 = ks[s],   k1 = ks[s+1], k2 = ks[s+2], k3 = ks[s+3];
        float v0 = vs[s],   v1 = vs[s+1], v2 = vs[s+2], v3 = vs[s+3];
        float4 a0l = *(const float4*)&g_At[k0 * MDIM + m0];
        float4 a0h = *(const float4*)&g_At[k0 * MDIM + m0 + 4];
        float4 a1l = *(const float4*)&g_At[k1 * MDIM + m0];
        float4 a1h = *(const float4*)&g_At[k1 * MDIM + m0 + 4];
        float4 a2l = *(const float4*)&g_At[k2 * MDIM + m0];
        float4 a2h = *(const float4*)&g_At[k2 * MDIM + m0 + 4];
        float4 a3l = *(const float4*)&g_At[k3 * MDIM + m0];
        float4 a3h = *(const float4*)&g_At[k3 * MDIM + m0 + 4];
        acc[0]=fmaf(v0,a0l.x,acc[0]); acc[1]=fmaf(v0,a0l.y,acc[1]);
        acc[2]=fmaf(v0,a0l.z,acc[2]); acc[3]=fmaf(v0,a0l.w,acc[3]);
        acc[4]=fmaf(v0,a0h.x,acc[4]); acc[5]=fmaf(v0,a0h.y,acc[5]);
        acc[6]=fmaf(v0,a0h.z,acc[6]); acc[7]=fmaf(v0,a0h.w,acc[7]);
        acc[0]=fmaf(v1,a1l.x,acc[0]); acc[1]=fmaf(v1,a1l.y,acc[1]);
        acc[2]=fmaf(v1,a1l.z,acc[2]); acc[3]=fmaf(v1,a1l.w,acc[3]);
        acc[4]=fmaf(v1,a1h.x,acc[4]); acc[5]=fmaf(v1,a1h.y,acc[5]);
        acc[6]=fmaf(v1,a1h.z,acc[6]); acc[7]=fmaf(v1,a1h.w,acc[7]);
        acc[0]=fmaf(v2,a2l.x,acc[0]); acc[1]=fmaf(v2,a2l.y,acc[1]);
        acc[2]=fmaf(v2,a2l.z,acc[2]); acc[3]=fmaf(v2,a2l.w,acc[3]);
        acc[4]=fmaf(v2,a2h.x,acc[4]); acc[5]=fmaf(v2,a2h.y,acc[5]);
        acc[6]=fmaf(v2,a2h.z,acc[6]); acc[7]=fmaf(v2,a2h.w,acc[7]);
        acc[0]=fmaf(v3,a3l.x,acc[0]); acc[1]=fmaf(v3,a3l.y,acc[1]);
        acc[2]=fmaf(v3,a3l.z,acc[2]); acc[3]=fmaf(v3,a3l.w,acc[3]);
        acc[4]=fmaf(v3,a3h.x,acc[4]); acc[5]=fmaf(v3,a3h.y,acc[5]);
        acc[6]=fmaf(v3,a3h.z,acc[6]); acc[7]=fmaf(v3,a3h.w,acc[7]);
    }
    for (; s < cnt; s++) {
        int k = ks[s]; float v = vs[s];
        float4 al = *(const float4*)&g_At[k * MDIM + m0];
        float4 ah = *(const float4*)&g_At[k * MDIM + m0 + 4];
        acc[0]=fmaf(v,al.x,acc[0]); acc[1]=fmaf(v,al.y,acc[1]);
        acc[2]=fmaf(v,al.z,acc[2]); acc[3]=fmaf(v,al.w,acc[3]);
        acc[4]=fmaf(v,ah.x,acc[4]); acc[5]=fmaf(v,ah.y,acc[5]);
        acc[6]=fmaf(v,ah.z,acc[6]); acc[7]=fmaf(v,ah.w,acc[7]);
    }

    size_t go = (size_t)row * MDIM + m0;
    float4 x0 = *(const float4*)&x[go];
    float4 x1 = *(const float4*)&x[go + 4];
    *(float4*)&g_r[go]     = make_float4(x0.x - acc[0], x0.y - acc[1],
                                         x0.z - acc[2], x0.w - acc[3]);
    *(float4*)&g_r[go + 4] = make_float4(x1.x - acc[4], x1.y - acc[5],
                                         x1.z - acc[6], x1.w - acc[7]);
}

// ---------------- helper: masked shrink ----------------
__device__ __forceinline__ float sel_shrink(float v, float t, float tv) {
    float av = fabsf(v);
    if (av >= t && av >= tv) return v;          // support-selected: pass through
    return copysignf(fmaxf(av - t, 0.f), v);    // soft threshold
}

// ---- k_step: v = u + r @ W_i^T, exact per-row k-th-largest select, shrink, write u ----
// R1's FMA ordering exactly; loads replaced by a 3-stage cp.async pipeline
// (1 barrier/chunk). r source / u dest selected INSIDE device code.
__global__ void __launch_bounds__(256, 1) k_step(
    const float* __restrict__ x, float* out,
    const float* __restrict__ thr, int layer, int kth,
    int add_u, int r_from_x, int write_out)
{
    extern __shared__ __align__(16) float smem[];
    const uint32_t sb = smem_u32(smem);
    __shared__ unsigned int s_prefix[32];
    __shared__ int          s_krem[32];

    const float* r_in = r_from_x ? x : g_r;
    float*       uout = write_out ? out : g_u;

    const int  tid  = threadIdx.x;
    const int  lane = tid & 31;
    const long b0   = (long)blockIdx.x * 32;
    const int  rgrp = tid >> 6;       // rows rgrp*8 + rr
    const int  cgrp = tid & 63;       // cols cgrp*4 + j*256

    float acc[8][16];
    #pragma unroll
    for (int rr = 0; rr < 8; rr++)
        #pragma unroll
        for (int c = 0; c < 16; c++) acc[rr][c] = 0.f;

    const float* Wt = g_Wt + (size_t)layer * MDIM * NDIM;
    const int rrow = tid >> 3, rk = tid & 7;

#define LOADC(cc_) do {                                                           \
    int st_ = (cc_) % N_STAGES;                                                   \
    uint32_t sW_ = sb + st_ * STG_FLOATS * 4;                                     \
    uint32_t sR_ = sW_ + W_FLOATS * 4;                                            \
    int kc_ = (cc_) * 8;                                                          \
    _Pragma("unroll")                                                             \
    for (int j_ = 0; j_ < 8; j_++) {                                              \
        int f_ = tid + 256 * j_;              /* float4 index: 2048 total */      \
        int k_ = f_ >> 8, c4_ = f_ & 255;                                         \
        cp16(sW_ + (k_ * 1024 + c4_ * 4) * 4,                                     \
             Wt + (size_t)(kc_ + k_) * NDIM + c4_ * 4);                           \
    }                                                                             \
    cp4(sR_ + (rk * 32 + rrow) * 4,                                               \
        r_in + (size_t)(b0 + rrow) * MDIM + kc_ + rk);                            \
} while (0)

    LOADC(0); CP_COMMIT();
    LOADC(1); CP_COMMIT();

    const float t = thr[layer];
    for (int c = 0; c < 32; c++) {
        if (c < 31) { CP_WAIT1(); } else { CP_WAIT0(); }
        __syncthreads();
        if (c + 2 < 32) { LOADC(c + 2); CP_COMMIT(); }
        const float* ws = smem + (c % N_STAGES) * STG_FLOATS;
        const float* rs = ws + W_FLOATS;
        #pragma unroll
        for (int k = 0; k < 8; k++) {
            float a[8];
            #pragma unroll
            for (int rr = 0; rr < 8; rr++) a[rr] = rs[k * 32 + rgrp * 8 + rr];
            #pragma unroll
            for (int j = 0; j < 4; j++) {
                float4 w = *(const float4*)&ws[k * 1024 + cgrp * 4 + j * 256];
                #pragma unroll
                for (int rr = 0; rr < 8; rr++) {
                    acc[rr][j*4+0] += a[rr] * w.x;
                    acc[rr][j*4+1] += a[rr] * w.y;
                    acc[rr][j*4+2] += a[rr] * w.z;
                    acc[rr][j*4+3] += a[rr] * w.w;
                }
            }
        }
    }
#undef LOADC

    // v = u + acc
    if (add_u) {
        #pragma unroll
        for (int rr = 0; rr < 8; rr++) {
            size_t ro = (size_t)(b0 + rgrp * 8 + rr) * NDIM;
            #pragma unroll
            for (int j = 0; j < 4; j++) {
                float4 uv = *(const float4*)(g_u + ro + cgrp * 4 + j * 256);
                acc[rr][j*4+0] += uv.x; acc[rr][j*4+1] += uv.y;
                acc[rr][j*4+2] += uv.z; acc[rr][j*4+3] += uv.w;
            }
        }
    }

    // ---- exact k-th largest of |v| per row: 4-pass byte radix on fp32 bits ----
    // hist reuses pipeline smem (all cp.async complete; barrier below).
    unsigned int (*hist)[257] = (unsigned int (*)[257])smem;      // 32.9 KB
    __syncthreads();
    for (int q = tid; q < 32 * 257; q += 256) ((unsigned int*)hist)[q] = 0u;
    if (tid < 32) { s_prefix[tid] = 0u; s_krem[tid] = kth; }
    __syncthreads();

    #pragma unroll
    for (int p = 0; p < 4; p++) {
        const int shift = 24 - 8 * p;
        const unsigned int himask = (p == 0) ? 0u : (0xFFFFFFFFu << (shift + 8));
        unsigned int pfx[8];
        #pragma unroll
        for (int rr = 0; rr < 8; rr++) pfx[rr] = s_prefix[rgrp * 8 + rr];
        #pragma unroll
        for (int rr = 0; rr < 8; rr++) {
            const int row = rgrp * 8 + rr;
            #pragma unroll
            for (int idx = 0; idx < 16; idx++) {
                unsigned int key = __float_as_uint(acc[rr][idx]) & 0x7FFFFFFFu;
                bool active = ((key & himask) == pfx[rr]);
                unsigned int bal = __ballot_sync(0xFFFFFFFFu, active);
                if (active) {
                    unsigned int bin  = (key >> shift) & 0xFFu;
                    unsigned int same = __match_any_sync(bal, bin);
                    if ((int)(__ffs(same) - 1) == lane)
                        atomicAdd(&hist[row][bin], (unsigned int)__popc(same));
                }
            }
        }
        __syncthreads();
        if (tid < 32) {                                  // one thread per row: scan bins
            int krem = s_krem[tid];
            unsigned int cum = 0; int sel = 0;
            for (int b = 255; b >= 0; b--) {
                unsigned int c = hist[tid][b];
                if (cum + c >= (unsigned int)krem) { sel = b; break; }
                cum += c;
            }
            s_krem[tid]    = krem - (int)cum;
            s_prefix[tid] |= ((unsigned int)sel) << shift;
        }
        __syncthreads();
        if (p < 3) {
            for (int q = tid; q < 32 * 257; q += 256) ((unsigned int*)hist)[q] = 0u;
            __syncthreads();
        }
    }

    // ---- mask + shrink + store u_next ----
    #pragma unroll
    for (int rr = 0; rr < 8; rr++) {
        const int row = rgrp * 8 + rr;
        const float tv = __uint_as_float(s_prefix[row]);
        size_t ro = (size_t)(b0 + row) * NDIM;
        #pragma unroll
        for (int j = 0; j < 4; j++) {
            float4 o;
            o.x = sel_shrink(acc[rr][j*4+0], t, tv);
            o.y = sel_shrink(acc[rr][j*4+1], t, tv);
            o.z = sel_shrink(acc[rr][j*4+2], t, tv);
            o.w = sel_shrink(acc[rr][j*4+3], t, tv);
            *(float4*)(uout + ro + cgrp * 4 + j * 256) = o;
        }
    }
}

// ------- compaction: dense u -> ascending (k, value) support lists -------
__global__ void __launch_bounds__(256, 1) k_compact() {
    const int tid = threadIdx.x, lane = tid & 31;
    const long row = (long)blockIdx.x * 8 + (tid >> 5);
    const float* ur = g_u + (size_t)row * NDIM;
    unsigned short* sk = g_sk + (size_t)row * NDIM;
    float*          sv = g_sv + (size_t)row * NDIM;

    int base = 0;
    #pragma unroll
    for (int j = 0; j < 8; j++) {
        int kbase = (lane + j * 32) * 4;
        float4 u4 = *(const float4*)(ur + kbase);
        float o[4] = {u4.x, u4.y, u4.z, u4.w};
        unsigned m = (o[0] != 0.f ? 1u : 0u) | (o[1] != 0.f ? 2u : 0u)
                   | (o[2] != 0.f ? 4u : 0u) | (o[3] != 0.f ? 8u : 0u);
        int pc = __popc(m);
        int pre = pc;
        #pragma unroll
        for (int off = 1; off < 32; off <<= 1) {
            int t2 = __shfl_up_sync(0xFFFFFFFFu, pre, off);
            if (lane >= off) pre += t2;
        }
        int excl = pre - pc;
        int tot  = __shfl_sync(0xFFFFFFFFu, pre, 31);
        int slot0 = base + excl;
        #pragma unroll
        for (int cc = 0; cc < 4; cc++) {
            if (m & (1u << cc)) {
                int slot = slot0 + __popc(m & ((1u << cc) - 1));
                sk[slot] = (unsigned short)(kbase + cc);
                sv[slot] = o[cc];
            }
        }
        base += tot;
    }
    if (lane == 0) g_scnt[row] = base;
}

// ---------------- launch (NO __device__ symbols in any host expression) ----------------
extern "C" void kernel_launch(void* const* d_in, const int* in_sizes, int n_in,
                              void* d_out, int out_size) {
    const float* x   = (const float*)d_in[0];
    const float* A   = (const float*)d_in[1];
    const float* W   = (const float*)d_in[2];
    const float* thr = (const float*)d_in[3];
    float* out = (float*)d_out;

    cudaFuncSetAttribute(k_step, cudaFuncAttributeMaxDynamicSharedMemorySize, DYN_STEP);

    k_transA<<<(NDIM * MDIM + 255) / 256, 256>>>(A);
    k_transW<<<(DEPTH * MDIM * NDIM + 255) / 256, 256>>>(W);

    for (int i = 0; i < DEPTH; i++) {
        double p = (i + 1) * 1.2; if (p > 5.0) p = 5.0;
        int idx = (int)ceil((100.0 - p) / 100.0 * (double)NDIM) - 1;
        int kth = NDIM - idx;                       // k-th largest
        if (i > 0)
            k_rsparse<<<BATCH / 8, 256>>>(x);
        k_step<<<BATCH / 32, 256, DYN_STEP>>>(x, out, thr, i, kth,
                                    (i > 0) ? 1 : 0,            // add_u
                                    (i == 0) ? 1 : 0,           // r_from_x
                                    (i == DEPTH - 1) ? 1 : 0);  // write_out
        if (i < DEPTH - 1)
            k_compact<<<BATCH / 8, 256>>>();
    }
}